// round 7
// baseline (speedup 1.0000x reference)
#include <cuda_runtime.h>
#include <cuda_bf16.h>
#include <cstdint>

// FwFM second-order via mma.sync (HMMA, works on plain sm_103 target):
//   out[c] = sum_l x[l,c] * T[l,c],  T = L*X,  L = strict lower of S=(W+W^T)/2.
// bf16 3-split (Ahi*Bhi + Ahi*Blo + Alo*Bhi), fp32 accumulate.

#define KF 39
#define BD (8192 * 64)
#define NCOL 128            // columns per CTA
#define THREADS 256         // 8 warps, 16 cols each
#define KP 48               // fields padded to 3 k16 steps; M padded to 48 (3 m16)
#define PITCH 50            // Xt row pitch in bf16 elems (100B; 25 banks -> conflict-free)

typedef unsigned int u32;

static __device__ __forceinline__ void mma_bf16(float* d, const u32* a, u32 b0, u32 b1) {
    asm volatile(
        "mma.sync.aligned.m16n8k16.row.col.f32.bf16.bf16.f32 "
        "{%0,%1,%2,%3}, {%4,%5,%6,%7}, {%8,%9}, {%0,%1,%2,%3};"
        : "+f"(d[0]), "+f"(d[1]), "+f"(d[2]), "+f"(d[3])
        : "r"(a[0]), "r"(a[1]), "r"(a[2]), "r"(a[3]), "r"(b0), "r"(b1));
}

__global__ __launch_bounds__(THREADS, 2)
void fwfm_hmma(const float* __restrict__ x,
               const float* __restrict__ W,
               float* __restrict__ out) {
    __shared__ __align__(16) __nv_bfloat16 Ah[KP * KP];          // L hi, row-major [l][k]
    __shared__ __align__(16) __nv_bfloat16 Al[KP * KP];          // L lo
    __shared__ __align__(16) __nv_bfloat16 Xh[NCOL * PITCH];     // X^T hi, [col][k]
    __shared__ __align__(16) __nv_bfloat16 Xl[NCOL * PITCH];     // X^T lo

    const int tid = threadIdx.x;

    // Build A = strict-lower L of S, bf16-split, zero-padded to 48x48.
    for (int t = tid; t < KP * KP; t += THREADS) {
        int l = t / KP, k = t - l * KP;
        float v = (l < KF && k < l) ? 0.5f * (W[l * KF + k] + W[k * KF + l]) : 0.0f;
        __nv_bfloat16 h = __float2bfloat16(v);
        Ah[t] = h;
        Al[t] = __float2bfloat16(v - __bfloat162float(h));
    }

    // Load X tile [KF x 128] coalesced, split, store transposed [col][k], k zero-padded.
    const int colL = tid & 127;
    const int c0 = blockIdx.x * NCOL;
    for (int k = tid >> 7; k < KP; k += 2) {
        float v = (k < KF) ? x[(size_t)k * BD + c0 + colL] : 0.0f;
        __nv_bfloat16 h = __float2bfloat16(v);
        Xh[colL * PITCH + k] = h;
        Xl[colL * PITCH + k] = __float2bfloat16(v - __bfloat162float(h));
    }
    __syncthreads();

    const int warp = tid >> 5, lane = tid & 31;
    const int g = lane >> 2, tq = lane & 3;      // groupID, quad-thread
    const int n0 = warp * 16;                    // warp's local column base

    float d[3][2][4];
#pragma unroll
    for (int mt = 0; mt < 3; ++mt)
#pragma unroll
        for (int nt = 0; nt < 2; ++nt)
#pragma unroll
            for (int r = 0; r < 4; ++r) d[mt][nt][r] = 0.0f;

    // 3 passes: (Ahi,Bhi), (Ahi,Blo), (Alo,Bhi)
#pragma unroll
    for (int pass = 0; pass < 3; ++pass) {
        const __nv_bfloat16* As = (pass == 2) ? Al : Ah;
        const __nv_bfloat16* Bs = (pass == 1) ? Xl : Xh;
#pragma unroll
        for (int kt = 0; kt < 3; ++kt) {
            // A fragments (m16n8k16 row-major layout), plain LDS.32:
            //  a0=(g, 2tq..+1)  a1=(g+8, 2tq..+1)  a2=(g, 2tq+8..+9)  a3=(g+8, 2tq+8..+9)
            u32 a[3][4];
#pragma unroll
            for (int mt = 0; mt < 3; ++mt) {
                const u32* r0 = (const u32*)(As + (mt * 16 + g) * KP + kt * 16 + tq * 2);
                const u32* r8 = (const u32*)(As + (mt * 16 + g + 8) * KP + kt * 16 + tq * 2);
                a[mt][0] = r0[0];
                a[mt][1] = r8[0];
                a[mt][2] = r0[4];
                a[mt][3] = r8[4];
            }
#pragma unroll
            for (int nt = 0; nt < 2; ++nt) {
                // B fragment (col-major k16xn8): col n = g, rows k = 2tq..+1 (b0), +8 (b1)
                const u32* br = (const u32*)(Bs + (n0 + nt * 8 + g) * PITCH + kt * 16 + tq * 2);
                u32 b0 = br[0], b1 = br[4];
#pragma unroll
                for (int mt = 0; mt < 3; ++mt)
                    mma_bf16(d[mt][nt], a[mt], b0, b1);
            }
        }
    }

    // Epilogue: out[c] = sum_l x[l][c] * D[l][c]; thread holds D rows mt*16+g(+8),
    // cols n0+nt*8+2tq(+1). x reconstructed as hi+lo (padded rows are zero).
#pragma unroll
    for (int nt = 0; nt < 2; ++nt) {
        const int cc = n0 + nt * 8 + 2 * tq;
        float s0 = 0.0f, s1 = 0.0f;
#pragma unroll
        for (int mt = 0; mt < 3; ++mt) {
            const int l0 = mt * 16 + g;
            float xa0 = __bfloat162float(Xh[cc * PITCH + l0]) + __bfloat162float(Xl[cc * PITCH + l0]);
            float xb0 = __bfloat162float(Xh[(cc + 1) * PITCH + l0]) + __bfloat162float(Xl[(cc + 1) * PITCH + l0]);
            float xa8 = __bfloat162float(Xh[cc * PITCH + l0 + 8]) + __bfloat162float(Xl[cc * PITCH + l0 + 8]);
            float xb8 = __bfloat162float(Xh[(cc + 1) * PITCH + l0 + 8]) + __bfloat162float(Xl[(cc + 1) * PITCH + l0 + 8]);
            s0 = fmaf(xa0, d[mt][nt][0], s0);
            s1 = fmaf(xb0, d[mt][nt][1], s1);
            s0 = fmaf(xa8, d[mt][nt][2], s0);
            s1 = fmaf(xb8, d[mt][nt][3], s1);
        }
        // Reduce over the 8 g-lanes holding this column (lanes tq, tq+4, ..., tq+28).
#pragma unroll
        for (int sh = 4; sh <= 16; sh <<= 1) {
            s0 += __shfl_xor_sync(0xFFFFFFFFu, s0, sh);
            s1 += __shfl_xor_sync(0xFFFFFFFFu, s1, sh);
        }
        if (g == 0) {
            float2 r = make_float2(s0, s1);
            reinterpret_cast<float2*>(out + c0 + n0 + nt * 8)[tq] = r;
        }
    }
}

extern "C" void kernel_launch(void* const* d_in, const int* in_sizes, int n_in,
                              void* d_out, int out_size) {
    const float* x = (const float*)d_in[0];   // [39, 8192, 64] fp32
    const float* W = (const float*)d_in[1];   // [39, 39] fp32
    float* out = (float*)d_out;               // [8192, 64] fp32

    fwfm_hmma<<<BD / NCOL, THREADS>>>(x, W, out);
}

// round 8
// speedup vs baseline: 5.8748x; 5.8748x over previous
#include <cuda_runtime.h>
#include <cuda_fp16.h>
#include <cstdint>

// FwFM second-order via mma.sync fp16 (plain sm_103 target):
//   out[c] = sum_l x[l,c] * T[l,c],  T[l,c] = sum_{k<l} S[k,l] x[k,c].
// Operand-swapped GEMM: A = X^T (M=cols, row-major), B = L^T (K=fields, N=l, col-major).
// B fragments precomputed once into a __device__ blob (9 lower-triangle tiles only).

#define KF 39
#define BD (8192 * 64)
#define NCOL 256            // cols per CTA, 1 per thread in load phase
#define THREADS 256         // 8 warps x 32 cols
#define P2 58               // Xh pitch in halfs (k-extent 48); bank-clean both phases
#define NTILE 9

typedef unsigned int u32;

// Fragment blob: [tile][lane][2] u32 (b0,b1 of m16n8k16 col-major f16 B-frag)
__device__ u32 Bfrag_g[NTILE * 32 * 2];

__constant__ int c_kt[NTILE] = {0, 0, 0, 0, 0, 1, 1, 1, 2};
__constant__ int c_nt[NTILE] = {0, 1, 2, 3, 4, 2, 3, 4, 4};

__global__ void fwfm_prep(const float* __restrict__ W) {
    int t = threadIdx.x;
    if (t >= NTILE * 32) return;
    int tile = t >> 5, lane = t & 31;
    int g = lane >> 2, tq = lane & 3;
    int kt = c_kt[tile], nt = c_nt[tile];
    int l = nt * 8 + g;                       // B column n -> output row l
    int k0 = kt * 16 + 2 * tq;
    float v[4];
#pragma unroll
    for (int d = 0; d < 4; ++d) {
        int k = k0 + (d >> 1) * 8 + (d & 1);  // k0, k0+1, k0+8, k0+9
        v[d] = (l < KF && k < l) ? 0.5f * (W[k * KF + l] + W[l * KF + k]) : 0.0f;
    }
    __half2 b0 = __floats2half2_rn(v[0], v[1]);
    __half2 b1 = __floats2half2_rn(v[2], v[3]);
    Bfrag_g[(tile * 32 + lane) * 2 + 0] = *(u32*)&b0;
    Bfrag_g[(tile * 32 + lane) * 2 + 1] = *(u32*)&b1;
}

static __device__ __forceinline__ void mma_f16(float* d, const u32* a, u32 b0, u32 b1) {
    asm volatile(
        "mma.sync.aligned.m16n8k16.row.col.f32.f16.f16.f32 "
        "{%0,%1,%2,%3}, {%4,%5,%6,%7}, {%8,%9}, {%0,%1,%2,%3};"
        : "+f"(d[0]), "+f"(d[1]), "+f"(d[2]), "+f"(d[3])
        : "r"(a[0]), "r"(a[1]), "r"(a[2]), "r"(a[3]), "r"(b0), "r"(b1));
}

__global__ __launch_bounds__(THREADS, 2)
void fwfm_main(const float* __restrict__ x, float* __restrict__ out) {
    __shared__ __half Xh[NCOL * P2];          // [col][k], k 0..47 (39.. zero), ~29.7 KB

    const int tid = threadIdx.x;
    const int c0 = blockIdx.x * NCOL;

    // Load this thread's column (coalesced across tid), convert to f16, pad to 48.
    {
        __half2* dst = reinterpret_cast<__half2*>(Xh + tid * P2);
#pragma unroll
        for (int kp = 0; kp < 24; ++kp) {
            float v0 = (2 * kp < KF) ? x[(size_t)(2 * kp) * BD + c0 + tid] : 0.0f;
            float v1 = (2 * kp + 1 < KF) ? x[(size_t)(2 * kp + 1) * BD + c0 + tid] : 0.0f;
            dst[kp] = __floats2half2_rn(v0, v1);
        }
    }
    __syncwarp();   // warp w's lanes loaded exactly warp w's 32 columns

    const int lane = tid & 31;
    const int g = lane >> 2, tq = lane & 3;
    const int cw = (tid >> 5) * 32;           // warp's local column base

    // Preload all 9 B fragments (coalesced LDG.64, L2-broadcast).
    u32 bf[NTILE][2];
#pragma unroll
    for (int t = 0; t < NTILE; ++t) {
        ulonglong1 q = reinterpret_cast<const ulonglong1*>(Bfrag_g)[t * 32 + lane];
        bf[t][0] = (u32)q.x;
        bf[t][1] = (u32)(q.x >> 32);
    }

    float d[2][5][4];
#pragma unroll
    for (int mt = 0; mt < 2; ++mt)
#pragma unroll
        for (int nt = 0; nt < 5; ++nt)
#pragma unroll
            for (int r = 0; r < 4; ++r) d[mt][nt][r] = 0.0f;

#pragma unroll
    for (int mt = 0; mt < 2; ++mt) {
#pragma unroll
        for (int kt = 0; kt < 3; ++kt) {
            // A fragment (row-major m16): rows = cols c, k = fields.
            const __half* ap = Xh + (cw + mt * 16 + g) * P2 + kt * 16 + 2 * tq;
            u32 a[4];
            a[0] = *(const u32*)(ap);
            a[1] = *(const u32*)(ap + 8 * P2);
            a[2] = *(const u32*)(ap + 8);
            a[3] = *(const u32*)(ap + 8 * P2 + 8);
            // Tiles sharing this kt: kt0 -> tiles 0..4, kt1 -> 5..7, kt2 -> 8.
            if (kt == 0) {
#pragma unroll
                for (int t = 0; t < 5; ++t) mma_f16(d[mt][t], a, bf[t][0], bf[t][1]);
            } else if (kt == 1) {
#pragma unroll
                for (int t = 5; t < 8; ++t) mma_f16(d[mt][t - 3], a, bf[t][0], bf[t][1]);
            } else {
                mma_f16(d[mt][4], a, bf[8][0], bf[8][1]);
            }
        }
    }

    // Epilogue: out[c] = sum_l x[l,c]*T[l,c]. Thread holds T rows c=g,g+8 (per mt),
    // cols l = nt*8+2tq,+1. x re-read from Xh (f16) as one LDS.32 per (c,nt).
#pragma unroll
    for (int mt = 0; mt < 2; ++mt) {
        float sg = 0.0f, sg8 = 0.0f;
        const __half* xg = Xh + (cw + mt * 16 + g) * P2;
        const __half* xg8 = xg + 8 * P2;
#pragma unroll
        for (int nt = 0; nt < 5; ++nt) {
            const int l0 = nt * 8 + 2 * tq;
            float2 fa = __half22float2(*(const __half2*)(xg + l0));
            float2 fb = __half22float2(*(const __half2*)(xg8 + l0));
            sg = fmaf(fa.x, d[mt][nt][0], sg);
            sg = fmaf(fa.y, d[mt][nt][1], sg);
            sg8 = fmaf(fb.x, d[mt][nt][2], sg8);
            sg8 = fmaf(fb.y, d[mt][nt][3], sg8);
        }
        // Sum over tq lanes (l-space partition): quad reduction.
        sg += __shfl_xor_sync(0xFFFFFFFFu, sg, 1);
        sg += __shfl_xor_sync(0xFFFFFFFFu, sg, 2);
        sg8 += __shfl_xor_sync(0xFFFFFFFFu, sg8, 1);
        sg8 += __shfl_xor_sync(0xFFFFFFFFu, sg8, 2);
        if (tq == 0) {
            out[c0 + cw + mt * 16 + g] = sg;
            out[c0 + cw + mt * 16 + g + 8] = sg8;
        }
    }
}

extern "C" void kernel_launch(void* const* d_in, const int* in_sizes, int n_in,
                              void* d_out, int out_size) {
    const float* x = (const float*)d_in[0];   // [39, 8192, 64] fp32
    const float* W = (const float*)d_in[1];   // [39, 39] fp32
    float* out = (float*)d_out;               // [8192, 64] fp32

    fwfm_prep<<<1, NTILE * 32>>>(W);
    fwfm_main<<<BD / NCOL, THREADS>>>(x, out);
}